// round 16
// baseline (speedup 1.0000x reference)
#include <cuda_runtime.h>
#include <cuda_bf16.h>
#include <cstdint>
#include <cstddef>

#define EPSBN 1e-5f

// Problem constants: b=4, c=64, h=256, w=512, kc=32
// Scratch (all bf16):
//   g_xt : [b][w][h] rows of 128B = x transposed, 64 c bf16
//   g_o  : [b][w][h] rows of 128B = 64 ch bf16
static __device__ __align__(16) uint32_t g_xt[4 * 512 * 256 * 32];
static __device__ __align__(16) uint32_t g_o [4 * 512 * 256 * 32];
// Prefolded weight image (bf16 pairs, SW128-swizzled [ch][c] rows) + bias
static __device__ __align__(16) uint32_t g_wimg[4096];
static __device__ float g_bias[128];

// ==================== helpers ====================
__device__ __forceinline__ uint32_t smem_u32(const void* p) {
    uint32_t a;
    asm("{ .reg .u64 t; cvta.to.shared.u64 t, %1; cvt.u32.u64 %0, t; }"
        : "=r"(a) : "l"(p));
    return a;
}
#define SWZ(o) ((o) ^ (((o) >> 3) & 0x70))

#define LDSM_X4(r0, r1, r2, r3, a)                                         \
    asm volatile("ldmatrix.sync.aligned.m8n8.x4.shared.b16 "               \
                 "{%0, %1, %2, %3}, [%4];"                                 \
                 : "=r"(r0), "=r"(r1), "=r"(r2), "=r"(r3) : "r"(a) : "memory")
#define LDSM_X2(r0, r1, a)                                                 \
    asm volatile("ldmatrix.sync.aligned.m8n8.x2.shared.b16 "               \
                 "{%0, %1}, [%2];"                                         \
                 : "=r"(r0), "=r"(r1) : "r"(a) : "memory")
#define LDSM_X2T(r0, r1, a)                                                \
    asm volatile("ldmatrix.sync.aligned.m8n8.x2.trans.shared.b16 "         \
                 "{%0, %1}, [%2];"                                         \
                 : "=r"(r0), "=r"(r1) : "r"(a) : "memory")

__device__ __forceinline__ void mma16816(float* d, const uint32_t* a,
                                         const uint32_t* b) {
    asm volatile(
        "mma.sync.aligned.m16n8k16.row.col.f32.bf16.bf16.f32 "
        "{%0, %1, %2, %3}, {%4, %5, %6, %7}, {%8, %9}, {%0, %1, %2, %3};"
        : "+f"(d[0]), "+f"(d[1]), "+f"(d[2]), "+f"(d[3])
        : "r"(a[0]), "r"(a[1]), "r"(a[2]), "r"(a[3]), "r"(b[0]), "r"(b[1]));
}

__device__ __forceinline__ uint32_t bf16pk(float a, float b) {
    uint32_t r;
    asm("cvt.rn.bf16x2.f32 %0, %1, %2;" : "=r"(r) : "f"(b), "f"(a));
    return r;   // a -> lower halfword, b -> upper
}

// ---------------- Kernel 0: fold BN into W once ----------------
__global__ void __launch_bounds__(256) prep_kernel(
    const float* __restrict__ Wq, const float* __restrict__ qg,
    const float* __restrict__ qb, const float* __restrict__ qm,
    const float* __restrict__ qv,
    const float* __restrict__ Wk, const float* __restrict__ kg,
    const float* __restrict__ kb, const float* __restrict__ km,
    const float* __restrict__ kv,
    const float* __restrict__ Wv, const float* __restrict__ bvp)
{
    const int idx = blockIdx.x * 256 + threadIdx.x;   // 0..4095
    const int ch = idx >> 5;
    const int c2 = (idx & 31) * 2;
    float w0, w1;
    if (ch < 32) {
        const float s = qg[ch] * rsqrtf(qv[ch] + EPSBN);
        w0 = Wq[ch * 64 + c2] * s;
        w1 = Wq[ch * 64 + c2 + 1] * s;
    } else if (ch < 64) {
        const int r = ch - 32;
        const float s = kg[r] * rsqrtf(kv[r] + EPSBN);
        w0 = Wk[r * 64 + c2] * s;
        w1 = Wk[r * 64 + c2 + 1] * s;
    } else {
        w0 = Wv[(ch - 64) * 64 + c2];
        w1 = Wv[(ch - 64) * 64 + c2 + 1];
    }
    g_wimg[SWZ((uint32_t)(ch * 128 + c2 * 2)) >> 2] = bf16pk(w0, w1);

    if (idx < 128) {
        float bb;
        if (idx < 32) {
            const float s = qg[idx] * rsqrtf(qv[idx] + EPSBN);
            bb = qb[idx] - qm[idx] * s;
        } else if (idx < 64) {
            const int r = idx - 32;
            const float s = kg[r] * rsqrtf(kv[r] + EPSBN);
            bb = kb[r] - km[r] * s;
        } else {
            bb = bvp[idx - 64];
        }
        g_bias[idx] = bb;
    }
}

// ---------------- Kernel 1: x transpose to bf16 rows (per batch chunk) ----
__global__ void __launch_bounds__(256) xt_kernel(const float* __restrict__ x,
                                                 int chunk)
{
    __shared__ __align__(16) uint32_t ts[64 * 36];
    const int tid = threadIdx.x;
    const int P0  = (chunk * 2048 + blockIdx.x) * 64;
    const int b   = P0 >> 17;
    const int h   = (P0 & 131071) >> 9;
    const int w0p = P0 & 511;
    const float* xrow = x + (size_t)b * 8388608 + (size_t)h * 512 + w0p;

#pragma unroll
    for (int i = 0; i < 2; i++) {
        const int idx = tid + i * 256;          // 512: 32 c-pairs x 16 w-quads
        const int c2 = idx >> 4, w4 = idx & 15;
        float4 a = *(const float4*)(xrow + (size_t)(2 * c2) * 131072 + w4 * 4);
        float4 c = *(const float4*)(xrow + (size_t)(2 * c2 + 1) * 131072 + w4 * 4);
        ts[(w4 * 4 + 0) * 36 + c2] = bf16pk(a.x, c.x);
        ts[(w4 * 4 + 1) * 36 + c2] = bf16pk(a.y, c.y);
        ts[(w4 * 4 + 2) * 36 + c2] = bf16pk(a.z, c.z);
        ts[(w4 * 4 + 3) * 36 + c2] = bf16pk(a.w, c.w);
    }
    __syncthreads();

    const size_t rowg = ((size_t)(b * 512 + w0p)) * 256 + h;
#pragma unroll
    for (int i = 0; i < 2; i++) {
        const int idx = tid + i * 256;          // 512 uint4
        const int row = idx >> 3, u4 = idx & 7;
        const uint32_t* s = ts + row * 36 + u4 * 4;
        ((uint4*)g_xt)[(rowg + (size_t)row * 256) * 8 + u4] =
            make_uint4(s[0], s[1], s[2], s[3]);
    }
}

// ---------------- Kernel 2: fused proj + attention (per batch chunk) ------
// smem: X (becomes QK area) 32KB | W 16KB | V 32KB | bias 512B
static constexpr int SM_X  = 0;
static constexpr int SM_W  = 32768;
static constexpr int SM_V  = 49152;
static constexpr int SM_BI = 81920;
static constexpr int SM_TOT = 82432;

__global__ void __launch_bounds__(256, 2) attn_kernel(int chunk)
{
    extern __shared__ __align__(16) unsigned char sm[];
    const uint32_t sb = smem_u32(sm);
    const int tid  = threadIdx.x;
    const int lane = tid & 31;
    const int wid  = tid >> 5;
    const int bw   = chunk * 512 + blockIdx.x;
    const size_t rowbase = (size_t)bw * 256;

    // ---- stage X rows (swizzled uint4 copy) + W image + bias ----
    {
        const uint4* src = (const uint4*)g_xt + rowbase * 8;
#pragma unroll
        for (int i = 0; i < 8; i++) {
            const int idx = tid + i * 256;      // 2048 uint4
            const int row = idx >> 3, q4 = idx & 7;
            *(uint4*)(sm + SM_X + SWZ((uint32_t)(row * 128 + q4 * 16))) =
                src[idx];
        }
#pragma unroll
        for (int i = 0; i < 4; i++) {
            const int idx = tid + i * 256;      // 1024 uint4 = 16KB
            ((uint4*)(sm + SM_W))[idx] = ((const uint4*)g_wimg)[idx];
        }
        if (tid < 128) ((float*)(sm + SM_BI))[tid] = g_bias[tid];
    }
    __syncthreads();

    const int m0 = wid * 32;
    const int lr = lane & 7;
    const int lm = (lane >> 3) & 1;
    const int lq = lane >> 4;
    const float* bias = (const float*)(sm + SM_BI);
    const int chL = 2 * (lane & 3);             // D-frag channel offset

    // ---- X A-frags (rows = this warp's 32 h, cols = 64 c) ----
    uint32_t ax[2][4][4];
#pragma unroll
    for (int mt = 0; mt < 2; mt++) {
#pragma unroll
        for (int kk = 0; kk < 4; kk++) {
            const uint32_t a = SWZ((uint32_t)(
                (m0 + mt * 16 + lm * 8 + lr) * 128 + (kk * 16 + lq * 8) * 2));
            LDSM_X4(ax[mt][kk][0], ax[mt][kk][1], ax[mt][kk][2], ax[mt][kk][3],
                    sb + SM_X + a);
        }
    }

    // ---- Q GEMM -> repack D-frags directly into S A-frags ----
    uint32_t aq[2][2][4];
    {
        float dq[2][4][4];
#pragma unroll
        for (int mt = 0; mt < 2; mt++)
#pragma unroll
            for (int nt = 0; nt < 4; nt++) {
                const float b0 = bias[nt * 8 + chL];
                const float b1 = bias[nt * 8 + chL + 1];
                dq[mt][nt][0] = b0; dq[mt][nt][1] = b1;
                dq[mt][nt][2] = b0; dq[mt][nt][3] = b1;
            }
#pragma unroll
        for (int nt = 0; nt < 4; nt++) {
            const uint32_t wr = (uint32_t)((nt * 8 + lr) * 128);
#pragma unroll
            for (int kk = 0; kk < 4; kk++) {
                uint32_t bw2[2];
                LDSM_X2(bw2[0], bw2[1],
                        sb + SM_W + SWZ(wr + (kk * 16 + lm * 8) * 2));
                mma16816(dq[0][nt], ax[0][kk], bw2);
                mma16816(dq[1][nt], ax[1][kk], bw2);
            }
        }
#pragma unroll
        for (int mt = 0; mt < 2; mt++)
#pragma unroll
            for (int f = 0; f < 2; f++) {
                aq[mt][f][0] = bf16pk(dq[mt][2 * f][0],     dq[mt][2 * f][1]);
                aq[mt][f][1] = bf16pk(dq[mt][2 * f][2],     dq[mt][2 * f][3]);
                aq[mt][f][2] = bf16pk(dq[mt][2 * f + 1][0], dq[mt][2 * f + 1][1]);
                aq[mt][f][3] = bf16pk(dq[mt][2 * f + 1][2], dq[mt][2 * f + 1][3]);
            }
    }

    // ---- K GEMM -> STS into SM_X cols 32..63 (own rows; X cols read done) --
    {
        float dk[2][4][4];
#pragma unroll
        for (int mt = 0; mt < 2; mt++)
#pragma unroll
            for (int nt = 0; nt < 4; nt++) {
                const float b0 = bias[32 + nt * 8 + chL];
                const float b1 = bias[32 + nt * 8 + chL + 1];
                dk[mt][nt][0] = b0; dk[mt][nt][1] = b1;
                dk[mt][nt][2] = b0; dk[mt][nt][3] = b1;
            }
#pragma unroll
        for (int nt = 0; nt < 4; nt++) {
            const uint32_t wr = (uint32_t)((32 + nt * 8 + lr) * 128);
#pragma unroll
            for (int kk = 0; kk < 4; kk++) {
                uint32_t bw2[2];
                LDSM_X2(bw2[0], bw2[1],
                        sb + SM_W + SWZ(wr + (kk * 16 + lm * 8) * 2));
                mma16816(dk[0][nt], ax[0][kk], bw2);
                mma16816(dk[1][nt], ax[1][kk], bw2);
            }
        }
        const int rA = m0 + (lane >> 2);
#pragma unroll
        for (int mt = 0; mt < 2; mt++) {
            const int rowA = rA + mt * 16;
#pragma unroll
            for (int nt = 0; nt < 4; nt++) {
                const uint32_t col = 64 + nt * 16 + (lane & 3) * 4;
                *(uint32_t*)(sm + SM_X + SWZ((uint32_t)(rowA * 128) + col)) =
                    bf16pk(dk[mt][nt][0], dk[mt][nt][1]);
                *(uint32_t*)(sm + SM_X + SWZ((uint32_t)((rowA + 8) * 128) + col)) =
                    bf16pk(dk[mt][nt][2], dk[mt][nt][3]);
            }
        }
    }

    // ---- V GEMM -> STS into SM_V [g][64 d] rows ----
#pragma unroll
    for (int mt = 0; mt < 2; mt++) {
        float dv[8][4];
#pragma unroll
        for (int nt = 0; nt < 8; nt++) {
            const float b0 = bias[64 + nt * 8 + chL];
            const float b1 = bias[64 + nt * 8 + chL + 1];
            dv[nt][0] = b0; dv[nt][1] = b1; dv[nt][2] = b0; dv[nt][3] = b1;
        }
#pragma unroll
        for (int nt = 0; nt < 8; nt++) {
            const uint32_t wr = (uint32_t)((64 + nt * 8 + lr) * 128);
#pragma unroll
            for (int kk = 0; kk < 4; kk++) {
                uint32_t bw2[2];
                LDSM_X2(bw2[0], bw2[1],
                        sb + SM_W + SWZ(wr + (kk * 16 + lm * 8) * 2));
                mma16816(dv[nt], ax[mt][kk], bw2);
            }
        }
        const int rowA = m0 + mt * 16 + (lane >> 2);
#pragma unroll
        for (int nt = 0; nt < 8; nt++) {
            const uint32_t col = nt * 16 + (lane & 3) * 4;
            *(uint32_t*)(sm + SM_V + SWZ((uint32_t)(rowA * 128) + col)) =
                bf16pk(dv[nt][0], dv[nt][1]);
            *(uint32_t*)(sm + SM_V + SWZ((uint32_t)((rowA + 8) * 128) + col)) =
                bf16pk(dv[nt][2], dv[nt][3]);
        }
    }
    __syncthreads();

    // ---- attention ----
    float oa[2][8][4];
#pragma unroll
    for (int mt = 0; mt < 2; mt++)
#pragma unroll
        for (int nt = 0; nt < 8; nt++)
#pragma unroll
            for (int j = 0; j < 4; j++) oa[mt][nt][j] = 0.0f;
    float ls[2][2] = {{0.0f, 0.0f}, {0.0f, 0.0f}};

#pragma unroll 1
    for (int ck = 0; ck < 4; ck++) {
        const int gc = ck * 64;
#pragma unroll
        for (int kt = 0; kt < 4; kt++) {
            float s[2][2][4];
#pragma unroll
            for (int mt = 0; mt < 2; mt++)
#pragma unroll
                for (int j = 0; j < 2; j++)
#pragma unroll
                    for (int q = 0; q < 4; q++) s[mt][j][q] = 0.0f;

#pragma unroll
            for (int j = 0; j < 2; j++) {
                const int g0 = gc + (2 * kt + j) * 8;
                uint32_t b0[2], b1[2];
                const uint32_t krow = (uint32_t)(g0 + lr) * 128;
                LDSM_X2(b0[0], b0[1],
                        sb + SM_X + SWZ(krow + (32 + lm * 8) * 2));
                LDSM_X2(b1[0], b1[1],
                        sb + SM_X + SWZ(krow + (48 + lm * 8) * 2));
#pragma unroll
                for (int mt = 0; mt < 2; mt++) {
                    mma16816(s[mt][j], aq[mt][0], b0);
                    mma16816(s[mt][j], aq[mt][1], b1);
                }
            }

            uint32_t pa[2][4];
#pragma unroll
            for (int mt = 0; mt < 2; mt++) {
#pragma unroll
                for (int j = 0; j < 2; j++) {
                    const float e0 = __expf(s[mt][j][0]);
                    const float e1 = __expf(s[mt][j][1]);
                    const float e2 = __expf(s[mt][j][2]);
                    const float e3 = __expf(s[mt][j][3]);
                    ls[mt][0] += e0 + e1;
                    ls[mt][1] += e2 + e3;
                    pa[mt][2 * j]     = bf16pk(e0, e1);
                    pa[mt][2 * j + 1] = bf16pk(e2, e3);
                }
            }

            // PV: B-frags via trans ldmatrix on [g][d] rows
            const int g0 = gc + kt * 16;
            const uint32_t gr = (uint32_t)(g0 + lr + lm * 8) * 128;
#pragma unroll
            for (int nd = 0; nd < 8; nd++) {
                uint32_t bv[2];
                LDSM_X2T(bv[0], bv[1], sb + SM_V + SWZ(gr + nd * 16));
                mma16816(oa[0][nd], pa[0], bv);
                mma16816(oa[1][nd], pa[1], bv);
            }
        }
    }

#pragma unroll
    for (int mt = 0; mt < 2; mt++) {
#pragma unroll
        for (int j = 0; j < 2; j++) {
            float l = ls[mt][j];
            l += __shfl_xor_sync(0xFFFFFFFF, l, 1);
            l += __shfl_xor_sync(0xFFFFFFFF, l, 2);
            ls[mt][j] = 1.0f / l;
        }
    }

    // ---- staged O epilogue (reuse smem) ----
    __syncthreads();
    uint32_t* OS = (uint32_t*)sm;          // [256 rows][36 words]
#pragma unroll
    for (int mt = 0; mt < 2; mt++) {
        const int rowA = m0 + mt * 16 + (lane >> 2);
        const int rowB = rowA + 8;
#pragma unroll
        for (int nd = 0; nd < 8; nd++) {
            const int p = nd * 4 + (lane & 3);
            OS[rowA * 36 + p] = bf16pk(oa[mt][nd][0] * ls[mt][0],
                                       oa[mt][nd][1] * ls[mt][0]);
            OS[rowB * 36 + p] = bf16pk(oa[mt][nd][2] * ls[mt][1],
                                       oa[mt][nd][3] * ls[mt][1]);
        }
    }
    __syncthreads();

#pragma unroll
    for (int i = 0; i < 8; i++) {
        const int idx = tid + i * 256;      // 2048 uint4
        const int row = idx >> 3, w4 = idx & 7;
        const uint32_t* s = OS + row * 36 + w4 * 4;
        ((uint4*)g_o)[(rowbase + row) * 8 + w4] =
            make_uint4(s[0], s[1], s[2], s[3]);
    }
}

// ---------------- Kernel 3: transpose + gamma*O + x (per batch chunk) -----
__global__ void __launch_bounds__(256) out_kernel(
    const float* __restrict__ x,
    const float* __restrict__ gammap,
    float* __restrict__ out,
    int bb)
{
    __shared__ float tile[32][33];

    const int tx = threadIdx.x;
    const int ty = threadIdx.y;
    const int tid = ty * 32 + tx;
    const int wt = blockIdx.x & 15;
    const int dt = blockIdx.x >> 4;
    const int h  = blockIdx.y;
    const int b  = bb;

    const float gamma = gammap[0];

#pragma unroll
    for (int i = 0; i < 2; i++) {
        const int idx = tid + i * 256;
        const int w  = idx >> 4;
        const int dw = idx & 15;
        const uint32_t wv =
            g_o[((size_t)(b * 512 + wt * 32 + w) * 256 + h) * 32 + dt * 16 + dw];
        const __nv_bfloat162 b2 = *(const __nv_bfloat162*)&wv;
        const float2 f2 = __bfloat1622float2(b2);
        tile[w][dw * 2]     = f2.x;
        tile[w][dw * 2 + 1] = f2.y;
    }
    __syncthreads();

#pragma unroll
    for (int j = 0; j < 4; j++) {
        const int d = dt * 32 + ty + j * 8;
        const int w = wt * 32 + tx;
        const size_t oi = ((size_t)(b * 64 + d) * 256 + h) * 512 + w;
        out[oi] = gamma * tile[tx][ty + j * 8] + x[oi];
    }
}

// ---------------- launch: prioritized pipelined graph ----------------
extern "C" void kernel_launch(void* const* d_in, const int* in_sizes, int n_in,
                              void* d_out, int out_size)
{
    const float* x    = (const float*)d_in[0];
    const float* Wq   = (const float*)d_in[1];
    const float* qg   = (const float*)d_in[2];
    const float* qb   = (const float*)d_in[3];
    const float* qm   = (const float*)d_in[4];
    const float* qvv  = (const float*)d_in[5];
    const float* Wk   = (const float*)d_in[6];
    const float* kg   = (const float*)d_in[7];
    const float* kb   = (const float*)d_in[8];
    const float* km   = (const float*)d_in[9];
    const float* kvv  = (const float*)d_in[10];
    const float* Wv   = (const float*)d_in[11];
    const float* bvp  = (const float*)d_in[12];
    const float* gam  = (const float*)d_in[13];
    float* out = (float*)d_out;

    cudaFuncSetAttribute(attn_kernel,
                         cudaFuncAttributeMaxDynamicSharedMemorySize, SM_TOT);

    int prLo = 0, prHi = 0;
    cudaDeviceGetStreamPriorityRange(&prLo, &prHi);   // prHi = highest prio

    cudaStream_t s1, s2, s3;
    cudaStreamCreateWithPriority(&s1, cudaStreamNonBlocking, prHi);  // attn
    cudaStreamCreateWithPriority(&s2, cudaStreamNonBlocking, prLo);  // xt
    cudaStreamCreateWithPriority(&s3, cudaStreamNonBlocking, prLo);  // out
    cudaEvent_t ev0, evEnd, evXt[4], evAt[4];
    cudaEventCreateWithFlags(&ev0, cudaEventDisableTiming);
    cudaEventCreateWithFlags(&evEnd, cudaEventDisableTiming);
    for (int i = 0; i < 4; i++) {
        cudaEventCreateWithFlags(&evXt[i], cudaEventDisableTiming);
        cudaEventCreateWithFlags(&evAt[i], cudaEventDisableTiming);
    }

    // fork s1/s2/s3 from the origin stream
    cudaEventRecord(ev0, 0);
    cudaStreamWaitEvent(s1, ev0, 0);
    cudaStreamWaitEvent(s2, ev0, 0);
    cudaStreamWaitEvent(s3, ev0, 0);

    // s2 (low prio): prep + per-batch transposes
    prep_kernel<<<16, 256, 0, s2>>>(Wq, qg, qb, qm, qvv,
                                    Wk, kg, kb, km, kvv, Wv, bvp);
    for (int i = 0; i < 4; i++) {
        xt_kernel<<<2048, 256, 0, s2>>>(x, i);
        cudaEventRecord(evXt[i], s2);
    }

    // s1 (high prio): attention chunks
    for (int i = 0; i < 4; i++) {
        cudaStreamWaitEvent(s1, evXt[i], 0);
        attn_kernel<<<512, 256, SM_TOT, s1>>>(i);
        cudaEventRecord(evAt[i], s1);
    }

    // s3 (low prio): output chunks overlap later attention chunks
    for (int i = 0; i < 4; i++) {
        cudaStreamWaitEvent(s3, evAt[i], 0);
        out_kernel<<<dim3(32, 256, 1), dim3(32, 8), 0, s3>>>(x, gam, out, i);
    }

    // join back to origin stream (s1/s2 branches join through s3's waits)
    cudaEventRecord(evEnd, s3);
    cudaStreamWaitEvent(0, evEnd, 0);

    // destroy per-call resources (all branches joined; no further uses)
    cudaStreamDestroy(s1);
    cudaStreamDestroy(s2);
    cudaStreamDestroy(s3);
    cudaEventDestroy(ev0);
    cudaEventDestroy(evEnd);
    for (int i = 0; i < 4; i++) {
        cudaEventDestroy(evXt[i]);
        cudaEventDestroy(evAt[i]);
    }
}